// round 8
// baseline (speedup 1.0000x reference)
#include <cuda_runtime.h>
#include <cuda_bf16.h>
#include <cstdint>

// ---------------- problem constants ----------------
#define B_   8
#define K_   288
#define L_   16384
#define O_   64
#define NT   256
#define LT   256         // l-tile per CTA
#define CH   16          // k per chunk = one k-step
#define NCH  18
#define NKS  18
#define NSTG 4

// staging: [k=16][l=256 fp32 padded to 260] per stage
#define LSTR 260
#define STAGE_F (CH * LSTR)                 // 4160 floats
#define STAGE_B (STAGE_F * 4)               // 16640 bytes
#define ROW_B   (LSTR * 4)                  // 1040 bytes (16B-aligned)
#define CHUNK_TX (CH * 1024)                // 16384 bytes per chunk

// output staging aliases stage memory after drain: [l=256][o=64 pad 68]
#define SO_LD 68
#define SOUT_BYTES (LT * SO_LD * 4)         // 69632
// mbarriers live beyond both aliases
#define OFF_MBAR 69632
#define SMEM_BYTES (OFF_MBAR + 64)

// ---------------- prep outputs ----------------
__device__ uint2  g_wfrag[NKS * 8 * 32];    // B fragments [ks][nt][lane]
__device__ float4 g_wb4[O_ / 2];            // (w2,bias) pairs

__global__ void gauss_prep_kernel(const float* __restrict__ w,
                                  const float* __restrict__ bias) {
    int t = threadIdx.x;
    if (blockIdx.x < NKS) {
        int ks   = blockIdx.x;
        int nt   = t >> 5;
        int lane = t & 31;
        int k = ks * 16 + (lane & 3) * 2;
        int o = nt * 8 + (lane >> 2);
        __nv_bfloat162 b0 = __floats2bfloat162_rn(w[k * O_ + o], w[(k + 1) * O_ + o]);
        __nv_bfloat162 b1 = __floats2bfloat162_rn(w[(k + 8) * O_ + o], w[(k + 9) * O_ + o]);
        uint2 v;
        v.x = *reinterpret_cast<uint32_t*>(&b0);
        v.y = *reinterpret_cast<uint32_t*>(&b1);
        g_wfrag[(ks * 8 + nt) * 32 + lane] = v;
    } else {
        __shared__ float s_w2[O_];
        int o   = t >> 2;
        int sub = t & 3;
        float s = 0.f;
        #pragma unroll 8
        for (int k = sub; k < K_; k += 4) { float v = w[k * O_ + o]; s = fmaf(v, v, s); }
        s += __shfl_xor_sync(0xFFFFFFFF, s, 1);
        s += __shfl_xor_sync(0xFFFFFFFF, s, 2);
        if (sub == 0) s_w2[o] = s;
        __syncthreads();
        if (t < O_ / 2) {
            float4 r;
            r.x = s_w2[2 * t];     r.y = bias[2 * t];
            r.z = s_w2[2 * t + 1]; r.w = bias[2 * t + 1];
            g_wb4[t] = r;
        }
    }
}

// ---------------- PTX helpers ----------------
__device__ __forceinline__ uint32_t smem_u32(const void* p) {
    return (uint32_t)__cvta_generic_to_shared(p);
}
__device__ __forceinline__ void mbar_init(uint32_t mbar, uint32_t cnt) {
    asm volatile("mbarrier.init.shared.b64 [%0], %1;" :: "r"(mbar), "r"(cnt) : "memory");
}
__device__ __forceinline__ void mbar_expect_tx(uint32_t mbar, uint32_t bytes) {
    asm volatile("mbarrier.arrive.expect_tx.shared.b64 _, [%0], %1;"
                 :: "r"(mbar), "r"(bytes) : "memory");
}
__device__ __forceinline__ void mbar_wait(uint32_t mbar, uint32_t parity) {
    uint32_t done;
    asm volatile(
        "{\n\t.reg .pred p;\n\t"
        "mbarrier.try_wait.parity.acquire.cta.shared::cta.b64 p, [%1], %2;\n\t"
        "selp.b32 %0, 1, 0, p;\n\t}"
        : "=r"(done) : "r"(mbar), "r"(parity) : "memory");
    if (!done) {
        asm volatile(
            "{\n\t.reg .pred P1;\n\t"
            "WAIT_LOOP_%=:\n\t"
            "mbarrier.try_wait.parity.acquire.cta.shared::cta.b64 P1, [%0], %1, 0x989680;\n\t"
            "@P1 bra.uni WAIT_DONE_%=;\n\t"
            "bra.uni WAIT_LOOP_%=;\n\t"
            "WAIT_DONE_%=:\n\t}"
            :: "r"(mbar), "r"(parity) : "memory");
    }
}
__device__ __forceinline__ void bulk_cp(uint32_t dst_smem, const void* src,
                                        uint32_t bytes, uint32_t mbar) {
    asm volatile(
        "cp.async.bulk.shared::cta.global.mbarrier::complete_tx::bytes [%0], [%1], %2, [%3];"
        :: "r"(dst_smem), "l"(src), "r"(bytes), "r"(mbar) : "memory");
}
__device__ __forceinline__ uint32_t packbf(float lo, float hi) {
    __nv_bfloat162 h = __floats2bfloat162_rn(lo, hi);
    return *reinterpret_cast<uint32_t*>(&h);
}
__device__ __forceinline__ void mma16816(float* c,
                                         uint32_t a0, uint32_t a1, uint32_t a2, uint32_t a3,
                                         uint32_t b0, uint32_t b1) {
    asm volatile(
        "mma.sync.aligned.m16n8k16.row.col.f32.bf16.bf16.f32 "
        "{%0,%1,%2,%3}, {%4,%5,%6,%7}, {%8,%9}, {%0,%1,%2,%3};"
        : "+f"(c[0]), "+f"(c[1]), "+f"(c[2]), "+f"(c[3])
        : "r"(a0), "r"(a1), "r"(a2), "r"(a3), "r"(b0), "r"(b1));
}

extern __shared__ float g_stg[];

// Bulk-copy chunk c into stage (c&3): 16 rows x 1KB, one UBLKCP each.
// Called by warp 0 only. Lane 0 arms the barrier, lanes 0..15 issue rows.
__device__ __forceinline__ void issue_chunk_bulk(const float* __restrict__ xb,
                                                 int c, int lane,
                                                 uint32_t stg_base, uint32_t mbar) {
    if (lane == 0) mbar_expect_tx(mbar, CHUNK_TX);
    __syncwarp();
    if (lane < CH) {
        const float* src = xb + (size_t)(c * CH + lane) * L_;
        uint32_t dst = stg_base + (uint32_t)(c & (NSTG - 1)) * STAGE_B
                     + (uint32_t)lane * ROW_B;
        bulk_cp(dst, src, 1024, mbar);
    }
}

__global__ __launch_bounds__(NT, 2)
void gauss_main_kernel(const float* __restrict__ x,
                       const float* __restrict__ gamma_p,
                       float* __restrict__ out) {
    const int t    = threadIdx.x;
    const int warp = t >> 5;
    const int lane = t & 31;
    const int bx   = blockIdx.x;
    const int b    = bx >> 6;              // 64 l-tiles per batch
    const int l0   = (bx & 63) * LT;

    const float* xb = x + (size_t)b * K_ * L_ + l0;
    const uint32_t stg_base = smem_u32(g_stg);
    const uint32_t mbar0    = stg_base + OFF_MBAR;

    const int kc  = (lane & 3) * 2;
    const int llo = lane >> 2;
    const int lw  = warp * 32;             // warp's l offset within tile

    // init per-stage full-barriers
    if (t == 0) {
        #pragma unroll
        for (int s = 0; s < NSTG; ++s) mbar_init(mbar0 + s * 8, 1);
    }
    __syncthreads();

    float acc[2][8][4];
    #pragma unroll
    for (int s = 0; s < 2; ++s)
        #pragma unroll
        for (int i = 0; i < 8; ++i)
            #pragma unroll
            for (int j = 0; j < 4; ++j) acc[s][i][j] = 0.f;
    float x2a[2][2] = {{0.f, 0.f}, {0.f, 0.f}};

    // prologue: chunks 0..2 in flight (warp 0 issues)
    if (warp == 0) {
        #pragma unroll
        for (int p = 0; p < NSTG - 1; ++p)
            issue_chunk_bulk(xb, p, lane, stg_base, mbar0 + (p & (NSTG - 1)) * 8);
    }

    // ---------------- mainloop, 1 barrier per chunk ----------------
    #pragma unroll 1
    for (int c = 0; c < NCH; ++c) {
        mbar_wait(mbar0 + (c & (NSTG - 1)) * 8, (c >> 2) & 1);   // chunk c landed
        __syncthreads();                   // all warps past chunk c-1's reads

        // refill stage (c+3)&3 (held chunk c-1, consumed) with chunk c+3
        if (warp == 0 && c + NSTG - 1 < NCH)
            issue_chunk_bulk(xb, c + NSTG - 1, lane, stg_base,
                             mbar0 + ((c + NSTG - 1) & (NSTG - 1)) * 8);

        const float* st = g_stg + (c & (NSTG - 1)) * STAGE_F;
        const uint2* wf = g_wfrag + (c * 8) * 32 + lane;

        #pragma unroll
        for (int s = 0; s < 2; ++s) {
            const float* p0 = st + lw + s * 16 + llo;
            float vl0 = p0[(kc + 0) * LSTR];
            float vl1 = p0[(kc + 1) * LSTR];
            float vl8 = p0[(kc + 8) * LSTR];
            float vl9 = p0[(kc + 9) * LSTR];
            float vh0 = p0[(kc + 0) * LSTR + 8];
            float vh1 = p0[(kc + 1) * LSTR + 8];
            float vh8 = p0[(kc + 8) * LSTR + 8];
            float vh9 = p0[(kc + 9) * LSTR + 8];

            x2a[s][0] = fmaf(vl0, vl0, x2a[s][0]); x2a[s][0] = fmaf(vl1, vl1, x2a[s][0]);
            x2a[s][0] = fmaf(vl8, vl8, x2a[s][0]); x2a[s][0] = fmaf(vl9, vl9, x2a[s][0]);
            x2a[s][1] = fmaf(vh0, vh0, x2a[s][1]); x2a[s][1] = fmaf(vh1, vh1, x2a[s][1]);
            x2a[s][1] = fmaf(vh8, vh8, x2a[s][1]); x2a[s][1] = fmaf(vh9, vh9, x2a[s][1]);

            uint32_t A0 = packbf(vl0, vl1);
            uint32_t A1 = packbf(vh0, vh1);
            uint32_t A2 = packbf(vl8, vl9);
            uint32_t A3 = packbf(vh8, vh9);

            #pragma unroll
            for (int nt = 0; nt < 8; ++nt) {
                uint2 bb = wf[nt * 32];    // L1-resident
                mma16816(acc[s][nt], A0, A1, A2, A3, bb.x, bb.y);
            }
        }
    }

    // x2 reduction across the 4 lanes sharing each l row
    #pragma unroll
    for (int s = 0; s < 2; ++s)
        #pragma unroll
        for (int hh = 0; hh < 2; ++hh) {
            x2a[s][hh] += __shfl_xor_sync(0xFFFFFFFF, x2a[s][hh], 1);
            x2a[s][hh] += __shfl_xor_sync(0xFFFFFFFF, x2a[s][hh], 2);
        }

    // ---------------- epilogue: exp into smem, then coalesced stores --------
    __syncthreads();                       // all stages consumed; alias safe
    float* sOut = g_stg;                   // [LT][SO_LD]

    const float gamma = __ldg(gamma_p);
    #pragma unroll
    for (int s = 0; s < 2; ++s) {
        float* so = sOut + (size_t)(lw + s * 16) * SO_LD;
        #pragma unroll
        for (int nt = 0; nt < 8; ++nt) {
            const int o = nt * 8 + kc;
            float4 wb = g_wb4[nt * 4 + (lane & 3)];
            float2 r0, r1;
            r0.x = __expf(-gamma * (x2a[s][0] + wb.x - 2.f * acc[s][nt][0])) + wb.y;
            r0.y = __expf(-gamma * (x2a[s][0] + wb.z - 2.f * acc[s][nt][1])) + wb.w;
            r1.x = __expf(-gamma * (x2a[s][1] + wb.x - 2.f * acc[s][nt][2])) + wb.y;
            r1.y = __expf(-gamma * (x2a[s][1] + wb.z - 2.f * acc[s][nt][3])) + wb.w;
            *reinterpret_cast<float2*>(so + (size_t)llo * SO_LD + o)       = r0;
            *reinterpret_cast<float2*>(so + (size_t)(llo + 8) * SO_LD + o) = r1;
        }
    }
    __syncthreads();

    // flat copy: CTA's output region is 64 KB contiguous in gmem
    float* ob = out + ((size_t)b * L_ + l0) * O_;
    #pragma unroll
    for (int i = t; i < LT * (O_ / 4); i += NT) {   // 4096 float4s
        const int row = i >> 4;
        const int col = (i & 15) << 2;
        float4 v = *reinterpret_cast<const float4*>(sOut + (size_t)row * SO_LD + col);
        *reinterpret_cast<float4*>(ob + (size_t)row * O_ + col) = v;
    }
}

extern "C" void kernel_launch(void* const* d_in, const int* in_sizes, int n_in,
                              void* d_out, int out_size) {
    const float* x     = (const float*)d_in[0];
    const float* w     = (const float*)d_in[1];
    const float* bias  = (const float*)d_in[2];
    const float* gamma = (const float*)d_in[3];
    float* out = (float*)d_out;

    cudaFuncSetAttribute(gauss_main_kernel,
                         cudaFuncAttributeMaxDynamicSharedMemorySize, SMEM_BYTES);

    gauss_prep_kernel<<<NKS + 1, NT>>>(w, bias);
    gauss_main_kernel<<<B_ * (L_ / LT), NT, SMEM_BYTES>>>(x, gamma, out);
    (void)in_sizes; (void)n_in; (void)out_size;
}

// round 9
// speedup vs baseline: 1.0929x; 1.0929x over previous
#include <cuda_runtime.h>
#include <cuda.h>
#include <cuda_bf16.h>
#include <cstdint>

// ---------------- problem constants ----------------
#define B_   8
#define K_   288
#define L_   16384
#define O_   64
#define NT   256
#define LT   256         // l-tile per CTA
#define CH   16          // k per chunk = one k-step
#define NCH  18
#define NKS  18
#define NSTG 4

#define STAGE_B   16384                     // 16 k-rows x 8 segs x 128B, dense
#define STAGE_F   4096
#define CHUNK_TX  16384
#define OFF_MBAR  (NSTG * STAGE_B)          // 65536
#define SMEM_BYTES (OFF_MBAR + 64)

// ---------------- prep outputs ----------------
__device__ uint2  g_wfrag[NKS * 8 * 32];    // B fragments [ks][nt][lane]
__device__ float4 g_wb4[O_ / 2];            // (w2,bias) pairs

__global__ void gauss_prep_kernel(const float* __restrict__ w,
                                  const float* __restrict__ bias) {
    int t = threadIdx.x;
    if (blockIdx.x < NKS) {
        int ks   = blockIdx.x;
        int nt   = t >> 5;
        int lane = t & 31;
        int k = ks * 16 + (lane & 3) * 2;
        int o = nt * 8 + (lane >> 2);
        __nv_bfloat162 b0 = __floats2bfloat162_rn(w[k * O_ + o], w[(k + 1) * O_ + o]);
        __nv_bfloat162 b1 = __floats2bfloat162_rn(w[(k + 8) * O_ + o], w[(k + 9) * O_ + o]);
        uint2 v;
        v.x = *reinterpret_cast<uint32_t*>(&b0);
        v.y = *reinterpret_cast<uint32_t*>(&b1);
        g_wfrag[(ks * 8 + nt) * 32 + lane] = v;
    } else {
        __shared__ float s_w2[O_];
        int o   = t >> 2;
        int sub = t & 3;
        float s = 0.f;
        #pragma unroll 8
        for (int k = sub; k < K_; k += 4) { float v = w[k * O_ + o]; s = fmaf(v, v, s); }
        s += __shfl_xor_sync(0xFFFFFFFF, s, 1);
        s += __shfl_xor_sync(0xFFFFFFFF, s, 2);
        if (sub == 0) s_w2[o] = s;
        __syncthreads();
        if (t < O_ / 2) {
            float4 r;
            r.x = s_w2[2 * t];     r.y = bias[2 * t];
            r.z = s_w2[2 * t + 1]; r.w = bias[2 * t + 1];
            g_wb4[t] = r;
        }
    }
}

// ---------------- PTX helpers ----------------
__device__ __forceinline__ uint32_t smem_u32(const void* p) {
    return (uint32_t)__cvta_generic_to_shared(p);
}
__device__ __forceinline__ void mbar_init(uint32_t mbar, uint32_t cnt) {
    asm volatile("mbarrier.init.shared.b64 [%0], %1;" :: "r"(mbar), "r"(cnt) : "memory");
}
__device__ __forceinline__ void mbar_expect_tx(uint32_t mbar, uint32_t bytes) {
    asm volatile("mbarrier.arrive.expect_tx.shared.b64 _, [%0], %1;"
                 :: "r"(mbar), "r"(bytes) : "memory");
}
__device__ __forceinline__ void mbar_wait(uint32_t mbar, uint32_t parity) {
    uint32_t done;
    asm volatile(
        "{\n\t.reg .pred p;\n\t"
        "mbarrier.try_wait.parity.acquire.cta.shared::cta.b64 p, [%1], %2;\n\t"
        "selp.b32 %0, 1, 0, p;\n\t}"
        : "=r"(done) : "r"(mbar), "r"(parity) : "memory");
    if (!done) {
        asm volatile(
            "{\n\t.reg .pred P1;\n\t"
            "WAIT_LOOP_%=:\n\t"
            "mbarrier.try_wait.parity.acquire.cta.shared::cta.b64 P1, [%0], %1, 0x989680;\n\t"
            "@P1 bra.uni WAIT_DONE_%=;\n\t"
            "bra.uni WAIT_LOOP_%=;\n\t"
            "WAIT_DONE_%=:\n\t}"
            :: "r"(mbar), "r"(parity) : "memory");
    }
}
__device__ __forceinline__ void tma_load_3d(uint32_t dst, const CUtensorMap* tmap,
                                            int cx, int cy, int cz, uint32_t mbar) {
    asm volatile(
        "cp.async.bulk.tensor.3d.shared::cta.global.tile.mbarrier::complete_tx::bytes "
        "[%0], [%1, {%2, %3, %4}], [%5];"
        :: "r"(dst), "l"(tmap), "r"(cx), "r"(cy), "r"(cz), "r"(mbar) : "memory");
}
__device__ __forceinline__ uint32_t packbf(float lo, float hi) {
    __nv_bfloat162 h = __floats2bfloat162_rn(lo, hi);
    return *reinterpret_cast<uint32_t*>(&h);
}
__device__ __forceinline__ void mma16816(float* c,
                                         uint32_t a0, uint32_t a1, uint32_t a2, uint32_t a3,
                                         uint32_t b0, uint32_t b1) {
    asm volatile(
        "mma.sync.aligned.m16n8k16.row.col.f32.bf16.bf16.f32 "
        "{%0,%1,%2,%3}, {%4,%5,%6,%7}, {%8,%9}, {%0,%1,%2,%3};"
        : "+f"(c[0]), "+f"(c[1]), "+f"(c[2]), "+f"(c[3])
        : "r"(a0), "r"(a1), "r"(a2), "r"(a3), "r"(b0), "r"(b1));
}

extern __shared__ __align__(1024) char g_sm[];

__global__ __launch_bounds__(NT, 2)
void gauss_main_kernel(const __grid_constant__ CUtensorMap tmap,
                       const float* __restrict__ gamma_p,
                       float* __restrict__ out) {
    const int t    = threadIdx.x;
    const int warp = t >> 5;
    const int lane = t & 31;
    const int bx   = blockIdx.x;
    const int b    = bx >> 6;              // 64 l-tiles per batch
    const int l0   = (bx & 63) * LT;

    const uint32_t stg_base = smem_u32(g_sm);
    const uint32_t mbar0    = stg_base + OFF_MBAR;

    const int kc  = (lane & 3) * 2;
    const int llo = lane >> 2;
    const int w512 = warp * 512;           // warp's seg-tile (floats)

    if (t == 0) {
        #pragma unroll
        for (int s = 0; s < NSTG; ++s) mbar_init(mbar0 + s * 8, 1);
    }
    __syncthreads();

    float acc[2][8][4];
    #pragma unroll
    for (int s = 0; s < 2; ++s)
        #pragma unroll
        for (int i = 0; i < 8; ++i)
            #pragma unroll
            for (int j = 0; j < 4; ++j) acc[s][i][j] = 0.f;
    float x2a[2][2] = {{0.f, 0.f}, {0.f, 0.f}};

    // prologue: 3 chunks in flight (warp 0; 8 lanes issue one 2KB TMA each)
    if (warp == 0) {
        #pragma unroll
        for (int p = 0; p < NSTG - 1; ++p) {
            uint32_t mb = mbar0 + (p & (NSTG - 1)) * 8;
            if (lane == 0) mbar_expect_tx(mb, CHUNK_TX);
            __syncwarp();
            if (lane < 8)
                tma_load_3d(stg_base + (p & (NSTG - 1)) * STAGE_B + lane * 2048,
                            &tmap, l0 + lane * 32, p * CH, b, mb);
        }
    }

    // ---------------- mainloop, 1 barrier per chunk ----------------
    #pragma unroll 1
    for (int c = 0; c < NCH; ++c) {
        mbar_wait(mbar0 + (c & (NSTG - 1)) * 8, (c >> 2) & 1);   // chunk c landed
        __syncthreads();                   // all warps past chunk c-1's reads

        // refill stage (c+3)&3 with chunk c+3
        if (warp == 0 && c + NSTG - 1 < NCH) {
            const int j = c + NSTG - 1;
            uint32_t mb = mbar0 + (j & (NSTG - 1)) * 8;
            if (lane == 0) mbar_expect_tx(mb, CHUNK_TX);
            __syncwarp();
            if (lane < 8)
                tma_load_3d(stg_base + (j & (NSTG - 1)) * STAGE_B + lane * 2048,
                            &tmap, l0 + lane * 32, j * CH, b, mb);
        }

        const float* stf = (const float*)(g_sm + (c & (NSTG - 1)) * STAGE_B);
        const uint2* wf  = g_wfrag + (c * 8) * 32 + lane;

        #pragma unroll
        for (int s = 0; s < 2; ++s) {
            const int li0 = s * 16 + llo;
            const int a0  = li0 ^ (kc << 2);          // swizzled col, k-even
            const int a1  = li0 ^ ((kc + 1) << 2);    // swizzled col, k-odd
            const int kb  = w512 + kc * 32;

            float vl0 = stf[kb + a0];
            float vl1 = stf[kb + 32 + a1];
            float vl8 = stf[kb + 256 + a0];
            float vl9 = stf[kb + 288 + a1];
            float vh0 = stf[kb + (a0 ^ 8)];
            float vh1 = stf[kb + 32 + (a1 ^ 8)];
            float vh8 = stf[kb + 256 + (a0 ^ 8)];
            float vh9 = stf[kb + 288 + (a1 ^ 8)];

            x2a[s][0] = fmaf(vl0, vl0, x2a[s][0]); x2a[s][0] = fmaf(vl1, vl1, x2a[s][0]);
            x2a[s][0] = fmaf(vl8, vl8, x2a[s][0]); x2a[s][0] = fmaf(vl9, vl9, x2a[s][0]);
            x2a[s][1] = fmaf(vh0, vh0, x2a[s][1]); x2a[s][1] = fmaf(vh1, vh1, x2a[s][1]);
            x2a[s][1] = fmaf(vh8, vh8, x2a[s][1]); x2a[s][1] = fmaf(vh9, vh9, x2a[s][1]);

            uint32_t A0 = packbf(vl0, vl1);
            uint32_t A1 = packbf(vh0, vh1);
            uint32_t A2 = packbf(vl8, vl9);
            uint32_t A3 = packbf(vh8, vh9);

            #pragma unroll
            for (int nt = 0; nt < 8; ++nt) {
                uint2 bb = wf[nt * 32];    // L1-resident
                mma16816(acc[s][nt], A0, A1, A2, A3, bb.x, bb.y);
            }
        }
    }

    // x2 reduction across the 4 lanes sharing each l row
    #pragma unroll
    for (int s = 0; s < 2; ++s)
        #pragma unroll
        for (int hh = 0; hh < 2; ++hh) {
            x2a[s][hh] += __shfl_xor_sync(0xFFFFFFFF, x2a[s][hh], 1);
            x2a[s][hh] += __shfl_xor_sync(0xFFFFFFFF, x2a[s][hh], 2);
        }

    // ---------------- register epilogue (R6 style) ----------------
    const float gamma = __ldg(gamma_p);
    float* ob = out + ((size_t)b * L_ + l0 + warp * 32) * O_;

    #pragma unroll
    for (int s = 0; s < 2; ++s) {
        float* obs = ob + (size_t)(s * 16) * O_;
        #pragma unroll
        for (int nt = 0; nt < 8; ++nt) {
            const int o = nt * 8 + kc;
            float4 wb = g_wb4[nt * 4 + (lane & 3)];
            float2 r0, r1;
            r0.x = __expf(-gamma * (x2a[s][0] + wb.x - 2.f * acc[s][nt][0])) + wb.y;
            r0.y = __expf(-gamma * (x2a[s][0] + wb.z - 2.f * acc[s][nt][1])) + wb.w;
            r1.x = __expf(-gamma * (x2a[s][1] + wb.x - 2.f * acc[s][nt][2])) + wb.y;
            r1.y = __expf(-gamma * (x2a[s][1] + wb.z - 2.f * acc[s][nt][3])) + wb.w;
            *reinterpret_cast<float2*>(obs + (size_t)llo * O_ + o)       = r0;
            *reinterpret_cast<float2*>(obs + (size_t)(llo + 8) * O_ + o) = r1;
        }
    }
}

// ---------------- host ----------------
typedef CUresult (CUDAAPI *EncTiledFn)(
    CUtensorMap*, CUtensorMapDataType, cuuint32_t, void*,
    const cuuint64_t*, const cuuint64_t*, const cuuint32_t*, const cuuint32_t*,
    CUtensorMapInterleave, CUtensorMapSwizzle, CUtensorMapL2promotion,
    CUtensorMapFloatOOBfill);

extern "C" void kernel_launch(void* const* d_in, const int* in_sizes, int n_in,
                              void* d_out, int out_size) {
    const float* x     = (const float*)d_in[0];
    const float* w     = (const float*)d_in[1];
    const float* bias  = (const float*)d_in[2];
    const float* gamma = (const float*)d_in[3];
    float* out = (float*)d_out;

    static EncTiledFn enc = nullptr;
    if (!enc) {
        cudaDriverEntryPointQueryResult qr;
#if CUDART_VERSION >= 12050
        cudaGetDriverEntryPointByVersion("cuTensorMapEncodeTiled", (void**)&enc,
                                         12000, cudaEnableDefault, &qr);
#else
        cudaGetDriverEntryPoint("cuTensorMapEncodeTiled", (void**)&enc,
                                cudaEnableDefault, &qr);
#endif
    }

    CUtensorMap tmap;
    cuuint64_t dims[3]    = {(cuuint64_t)L_, (cuuint64_t)K_, (cuuint64_t)B_};
    cuuint64_t strides[2] = {(cuuint64_t)L_ * 4, (cuuint64_t)K_ * L_ * 4};
    cuuint32_t box[3]     = {32, CH, 1};
    cuuint32_t estr[3]    = {1, 1, 1};
    enc(&tmap, CU_TENSOR_MAP_DATA_TYPE_FLOAT32, 3, (void*)x,
        dims, strides, box, estr,
        CU_TENSOR_MAP_INTERLEAVE_NONE, CU_TENSOR_MAP_SWIZZLE_128B,
        CU_TENSOR_MAP_L2_PROMOTION_L2_128B, CU_TENSOR_MAP_FLOAT_OOB_FILL_NONE);

    cudaFuncSetAttribute(gauss_main_kernel,
                         cudaFuncAttributeMaxDynamicSharedMemorySize, SMEM_BYTES);

    gauss_prep_kernel<<<NKS + 1, NT>>>(w, bias);
    gauss_main_kernel<<<B_ * (L_ / LT), NT, SMEM_BYTES>>>(tmap, gamma, out);
    (void)in_sizes; (void)n_in; (void)out_size;
}